// round 16
// baseline (speedup 1.0000x reference)
#include <cuda_runtime.h>
#include <cstdint>

#define NC 32
#define NU 5
#define NV 5
#define NH 64
#define NW 64

#define TILE_H 8
#define CHSTRIDE (NU * NV * NH * NW)   // 102400
#define CHB      (CHSTRIDE * 4)

typedef unsigned long long u64;

// stage layout (floats); rows are 72 cols (4 | 64 | 4), 10 rows per plane
//  union (uvx+uvy): 9 planes x 720 = 6480 @ 0
//  uxy:             3 planes x 720 = 2160 @ 6480
//  vxy:             3 planes x 720 = 2160 @ 8640
//  w:               864             @ 10800
#define UXY_F   6480
#define VXY_F   8640
#define WB_F    10800
#define STAGEF  11680                   // padded (11664 used)
#define STAGEB  (STAGEF * 4)            // 46720 B
#define SMEM_BYTES (2 * STAGEB)         // 93440 B

// Reorganized weights: [c][branch][tap][o], tap = (ka*3+kb)*3+kg
__device__ __align__(128) float g_wr[NC * 864];
__device__ float g_bias[32];
__device__ float g_slope[4];

__global__ void prep_kernel(const float* __restrict__ w0, const float* __restrict__ w1,
                            const float* __restrict__ w2, const float* __restrict__ w3,
                            const float* __restrict__ b0, const float* __restrict__ b1,
                            const float* __restrict__ b2, const float* __restrict__ b3,
                            const float* __restrict__ a0, const float* __restrict__ a1,
                            const float* __restrict__ a2, const float* __restrict__ a3)
{
    int t = blockIdx.x * blockDim.x + threadIdx.x;
    if (t < NC * 864) {
        int o   = t & 7;
        int tap = (t >> 3) % 27;
        int br  = (t / 216) & 3;
        int c   = t / 864;
        const float* w = (br == 0) ? w0 : (br == 1) ? w1 : (br == 2) ? w2 : w3;
        g_wr[t] = w[(o * NC + c) * 27 + tap];
    }
    if (t < 32) {
        const float* b = (t < 8) ? b0 : (t < 16) ? b1 : (t < 24) ? b2 : b3;
        g_bias[t] = b[t & 7];
    }
    if (t < 4) {
        const float* a = (t == 0) ? a0 : (t == 1) ? a1 : (t == 2) ? a2 : a3;
        g_slope[t] = a[0];
    }
}

// ---------- helpers ----------
__device__ __forceinline__ uint32_t smem_u32(const void* p) {
    uint32_t a;
    asm("{ .reg .u64 t; cvta.to.shared.u64 t, %1; cvt.u32.u64 %0, t; }" : "=r"(a) : "l"(p));
    return a;
}
__device__ __forceinline__ void cp16(uint32_t dst, const void* src) {
    asm volatile("cp.async.cg.shared.global [%0], [%1], 16;" :: "r"(dst), "l"(src) : "memory");
}
__device__ __forceinline__ void cp_commit() {
    asm volatile("cp.async.commit_group;" ::: "memory");
}
__device__ __forceinline__ void cp_wait1() {
    asm volatile("cp.async.wait_group 1;" ::: "memory");
}
__device__ __forceinline__ void cp_wait0() {
    asm volatile("cp.async.wait_group 0;" ::: "memory");
}
__device__ __forceinline__ void bar_sync(int id, int cnt) {
    asm volatile("bar.sync %0, %1;" :: "r"(id), "r"(cnt) : "memory");
}
__device__ __forceinline__ void fma2(u64& acc, u64 a, u64 b) {
    asm("fma.rn.f32x2 %0, %1, %2, %0;" : "+l"(acc) : "l"(a), "l"(b));
}
__device__ __forceinline__ u64 splat2(float v) {
    u64 r;
    asm("mov.b64 %0, {%1, %1};" : "=l"(r) : "f"(v));
    return r;
}
__device__ __forceinline__ float2 unpack2(u64 v) {
    float2 r;
    asm("mov.b64 {%0, %1}, %2;" : "=f"(r.x), "=f"(r.y) : "l"(v));
    return r;
}

// packed-offset staging: NE entries, u16 16B-chunk indices (0xFFFF = skip)
template<int NE, int STRIDE_B>
__device__ __forceinline__ void stage_x(const uint32_t* pk, uint32_t dst,
                                        const char* xc)
{
    #pragma unroll
    for (int i = 0; i < NE; i++) {
        uint32_t h16 = (pk[i >> 1] >> (16 * (i & 1))) & 0xFFFFu;
        if (h16 != 0xFFFFu) cp16(dst + i * STRIDE_B, xc + (size_t)h16 * 16);
    }
}

// ===== compute: 4 h-points x 8 oc per thread =====
// acc[p][j]: h point p, oc pair (2j, 2j+1). Buffers: plane 720 fl, row 72 fl.

// uvx: rows (ho+p+kg), col cb (center)
__device__ __forceinline__ void comp_uvx(const float* __restrict__ sx,
                                         const float* __restrict__ sw,
                                         int cb, int ho, u64 (&acc)[4][4])
{
    #pragma unroll
    for (int ab = 0; ab < 9; ab++) {
        const float* col = sx + ab * 720 + ho * 72 + cb;
        u64 xs[6];
        #pragma unroll
        for (int r = 0; r < 6; r++) xs[r] = splat2(col[r * 72]);
        #pragma unroll
        for (int kg = 0; kg < 3; kg++) {
            const float* wp = sw + (ab * 3 + kg) * 8;
            ulonglong2 w01 = *(const ulonglong2*)wp;
            ulonglong2 w23 = *(const ulonglong2*)(wp + 4);
            #pragma unroll
            for (int p = 0; p < 4; p++) {
                u64 xx = xs[p + kg];
                fma2(acc[p][0], xx, w01.x);
                fma2(acc[p][1], xx, w01.y);
                fma2(acc[p][2], xx, w23.x);
                fma2(acc[p][3], xx, w23.y);
            }
        }
    }
}

// uvy: row ho+p+1, col cb-1+kg
__device__ __forceinline__ void comp_uvy(const float* __restrict__ sx,
                                         const float* __restrict__ sw,
                                         int cb, int ho, u64 (&acc)[4][4])
{
    #pragma unroll
    for (int ab = 0; ab < 9; ab++) {
        const float* plb = sx + ab * 720 + (ho + 1) * 72;
        #pragma unroll
        for (int kg = 0; kg < 3; kg++) {
            const float* col = plb + (cb - 1 + kg);
            const float* wp = sw + (ab * 3 + kg) * 8;
            ulonglong2 w01 = *(const ulonglong2*)wp;
            ulonglong2 w23 = *(const ulonglong2*)(wp + 4);
            #pragma unroll
            for (int p = 0; p < 4; p++) {
                u64 xx = splat2(col[p * 72]);
                fma2(acc[p][0], xx, w01.x);
                fma2(acc[p][1], xx, w01.y);
                fma2(acc[p][2], xx, w23.x);
                fma2(acc[p][3], xx, w23.y);
            }
        }
    }
}

// uxy/vxy: row ho+p+kb, col cb-1+kg (3 planes)
__device__ __forceinline__ void comp_hw(const float* __restrict__ sx,
                                        const float* __restrict__ sw,
                                        int cb, int ho, u64 (&acc)[4][4])
{
    #pragma unroll
    for (int ka = 0; ka < 3; ka++) {
        const float* plb = sx + ka * 720 + ho * 72;
        #pragma unroll
        for (int kg = 0; kg < 3; kg++) {
            const float* col = plb + (cb - 1 + kg);
            u64 xs[6];
            #pragma unroll
            for (int r = 0; r < 6; r++) xs[r] = splat2(col[r * 72]);
            #pragma unroll
            for (int kb = 0; kb < 3; kb++) {
                const float* wp = sw + ((ka * 3 + kb) * 3 + kg) * 8;
                ulonglong2 w01 = *(const ulonglong2*)wp;
                ulonglong2 w23 = *(const ulonglong2*)(wp + 4);
                #pragma unroll
                for (int p = 0; p < 4; p++) {
                    u64 xx = xs[p + kb];
                    fma2(acc[p][0], xx, w01.x);
                    fma2(acc[p][1], xx, w01.y);
                    fma2(acc[p][2], xx, w23.x);
                    fma2(acc[p][3], xx, w23.y);
                }
            }
        }
    }
}

// ===================== main kernel =====================
// 512 threads: wid>>2 = branch (one branch warp per SMSP), wid&3 = (h-half, w-half)
__global__ __launch_bounds__(512, 1)
void fe_kernel(const float* __restrict__ x, float* __restrict__ out)
{
    extern __shared__ __align__(16) float sm[];
    const uint32_t sbase = smem_u32(sm);

    const int tid = threadIdx.x;
    const int wid = tid >> 5;
    const int wl  = tid & 31;
    const int br  = wid >> 2;        // 0..3
    const int sub = wid & 3;
    const int ho  = (sub >> 1) * 4;  // h-half offset 0/4
    const int wh  = sub & 1;         // w-half

    const int th = blockIdx.x * TILE_H;   // 0..56
    const int uv = blockIdx.y;            // 0..24
    const int u  = uv / 5, v = uv % 5;
    const int b  = blockIdx.z;            // 0..7

    // one-time zero (halo + channel-invariant OOB chunks)
    float4* z = (float4*)sm;
    #pragma unroll
    for (int i = tid; i < (2 * STAGEF) / 4; i += 512)
        z[i] = make_float4(0.f, 0.f, 0.f, 0.f);
    __syncthreads();

    // ---- packed channel-invariant per-lane chunk indices ----
    uint32_t pk[4];
    #pragma unroll
    for (int i = 0; i < 4; i++) pk[i] = 0xFFFFFFFFu;

    int j;          // lane index within staging group
    if (br < 2) {
        // union buffer: 1620 chunks = 90 rows x 18 chunks; group = warps 0..7
        j = wid * 32 + wl;   // 0..255
        #pragma unroll
        for (int i = 0; i < 7; i++) {
            int k = j + 256 * i;
            uint32_t val = 0xFFFFu;
            if (k < 1620) {
                int row = k / 18, ch = k - row * 18;
                int ab = row / 10, r = row - ab * 10;
                int gu = u + ab / 3 - 1, gv = v + ab % 3 - 1;
                int gh = th + r - 1,     gw = ch * 4 - 4;
                if ((unsigned)gu < 5u && (unsigned)gv < 5u &&
                    (unsigned)gh < 64u && (unsigned)gw < 64u)
                    val = (uint32_t)((((gu * 5 + gv) * 64 + gh) * 64 + gw) >> 2);
            }
            int sh = 16 * (i & 1);
            pk[i >> 1] = (pk[i >> 1] & ~(0xFFFFu << sh)) | (val << sh);
        }
    } else {
        // uxy/vxy: 540 chunks = 30 rows x 18; groups = warps 8..11 / 12..15
        j = (wid & 3) * 32 + wl;  // 0..127
        #pragma unroll
        for (int i = 0; i < 5; i++) {
            int k = j + 128 * i;
            uint32_t val = 0xFFFFu;
            if (k < 540) {
                int row = k / 18, ch = k - row * 18;
                int pl = row / 10, r = row - pl * 10;
                int gu = (br == 2) ? (u + pl - 1) : u;
                int gv = (br == 2) ? v : (v + pl - 1);
                int gh = th + r - 1, gw = ch * 4 - 4;
                if ((unsigned)gu < 5u && (unsigned)gv < 5u &&
                    (unsigned)gh < 64u && (unsigned)gw < 64u)
                    val = (uint32_t)((((gu * 5 + gv) * 64 + gh) * 64 + gw) >> 2);
            }
            int sh = 16 * (i & 1);
            pk[i >> 1] = (pk[i >> 1] & ~(0xFFFFu << sh)) | (val << sh);
        }
    }

    // staging destinations
    const int xoff_f = (br < 2) ? 0 : (br == 2 ? UXY_F : VXY_F);
    uint32_t dstx[2], dstw[2];
    dstx[0] = sbase + xoff_f * 4 + j * 16;
    dstx[1] = dstx[0] + STAGEB;
    // w: uv group stages branches 0+1 (108 chunks, j<108 over warps 0..7);
    //    uxy stages br2 (54, j<54); vxy stages br3 (54)
    const int wsrc_off = (br < 2) ? 0 : (br == 2 ? 1728 : 2592);
    const int wcnt     = (br < 2) ? 108 : 54;
    dstw[0] = sbase + WB_F * 4 + wsrc_off + j * 16;
    dstw[1] = dstw[0] + STAGEB;

    const float* sx_p[2] = { sm + xoff_f,          sm + STAGEF + xoff_f };
    const float* sw_p[2] = { sm + WB_F + br * 216, sm + STAGEF + WB_F + br * 216 };

    const char* xb = (const char*)x + (size_t)b * NC * CHB;
    const char* wbg = (const char*)g_wr + wsrc_off;
    const bool do_w = (j < wcnt);

    const int cb = 4 + wh * 32 + wl;   // center column in 72-wide rows

    u64 acc[4][4];
    #pragma unroll
    for (int p = 0; p < 4; p++)
        #pragma unroll
        for (int jj = 0; jj < 4; jj++) acc[p][jj] = 0ull;

    const int bid  = (br < 2) ? 1 : br;              // barrier id 1 / 2 / 3
    const int bcnt = (br < 2) ? 256 : 128;

    // ---- stage channel 0 ----
    if (br < 2) stage_x<7, 4096>(pk, dstx[0], xb);
    else        stage_x<5, 2048>(pk, dstx[0], xb);
    if (do_w) cp16(dstw[0], wbg + j * 16);
    cp_commit();

    #pragma unroll 1
    for (int c = 0; c < NC; c++) {
        const int s = c & 1;
        if (c < NC - 1) {
            bar_sync(bid, bcnt);     // group done computing c-1 from buffer s^1
            const char* xc = xb + (size_t)(c + 1) * CHB;
            if (br < 2) stage_x<7, 4096>(pk, dstx[s ^ 1], xc);
            else        stage_x<5, 2048>(pk, dstx[s ^ 1], xc);
            if (do_w) cp16(dstw[s ^ 1], wbg + (size_t)(c + 1) * 3456 + j * 16);
            cp_commit();
            cp_wait1();              // own channel-c data complete
        } else {
            cp_wait0();
        }
        bar_sync(bid, bcnt);         // group's channel-c data complete + visible

        if (br == 0)      comp_uvx(sx_p[s], sw_p[s], cb, ho, acc);
        else if (br == 1) comp_uvy(sx_p[s], sw_p[s], cb, ho, acc);
        else              comp_hw (sx_p[s], sw_p[s], cb, ho, acc);
    }

    // ---- epilogue: bias + PReLU + store ----
    const float slope = g_slope[br];
    const int ocb = br * 8;
    const size_t base0 = (size_t)b * 32 * CHSTRIDE + (size_t)ocb * CHSTRIDE +
                         (size_t)uv * (NH * NW) + (size_t)(th + ho) * NW +
                         (size_t)(wh * 32 + wl);
    #pragma unroll
    for (int jj = 0; jj < 4; jj++) {
        const float b0 = g_bias[ocb + jj * 2];
        const float b1 = g_bias[ocb + jj * 2 + 1];
        const size_t cb0 = base0 + (size_t)(jj * 2) * CHSTRIDE;
        const size_t cb1 = base0 + (size_t)(jj * 2 + 1) * CHSTRIDE;
        #pragma unroll
        for (int p = 0; p < 4; p++) {
            float2 y = unpack2(acc[p][jj]);
            float y0 = y.x + b0;
            float y1 = y.y + b1;
            y0 = (y0 >= 0.f) ? y0 : slope * y0;
            y1 = (y1 >= 0.f) ? y1 : slope * y1;
            out[cb0 + (size_t)p * NW] = y0;
            out[cb1 + (size_t)p * NW] = y1;
        }
    }
}

extern "C" void kernel_launch(void* const* d_in, const int* in_sizes, int n_in,
                              void* d_out, int out_size)
{
    const float* x = (const float*)d_in[0];

    prep_kernel<<<(NC * 864 + 255) / 256, 256>>>(
        (const float*)d_in[1], (const float*)d_in[4],
        (const float*)d_in[7], (const float*)d_in[10],
        (const float*)d_in[2], (const float*)d_in[5],
        (const float*)d_in[8], (const float*)d_in[11],
        (const float*)d_in[3], (const float*)d_in[6],
        (const float*)d_in[9], (const float*)d_in[12]);

    static bool attr_set = false;
    if (!attr_set) {
        cudaFuncSetAttribute(fe_kernel, cudaFuncAttributeMaxDynamicSharedMemorySize,
                             SMEM_BYTES);
        attr_set = true;
    }

    dim3 grid(8, 25, 8);   // (h tiles, uv, batch); full-width tiles
    fe_kernel<<<grid, 512, SMEM_BYTES>>>(x, (float*)d_out);
}

// round 17
// speedup vs baseline: 1.3407x; 1.3407x over previous
#include <cuda_runtime.h>
#include <cstdint>

#define NC 32
#define NU 5
#define NV 5
#define NH 64
#define NW 64

#define TILE_H 4
#define TILE_W 32
#define CHSTRIDE (NU * NV * NH * NW)   // 102400
#define CHB      (CHSTRIDE * 4)

typedef unsigned long long u64;

// stage layout (floats):
//  union (uvx+uvy): 9 planes x 6 rows x 40 cols = 2160 @ 0   (plane 240 fl/960B, row 40 fl/160B)
//  uxy:             3 planes x 6 rows x 40 cols =  720 @ 2160
//  vxy:             3 planes x 6 rows x 40 cols =  720 @ 2880
//  w (mma order):   4 branches x 256            = 1024 @ 3600
#define UXY_F   2160
#define VXY_F   2880
#define WB_F    3600
#define STAGEF  4640                    // padded (4624 used)
#define STAGEB  (STAGEF * 4)            // 18560 B
#define SMEM_FLOATS (2 * STAGEF)        // 9280 (37120 B)

// mma-ordered tf32 weights: [c][br][kc][tig][n][2] = [c][br][256]
__device__ __align__(128) float g_w2[NC * 4 * 256];
__device__ float g_bias[32];
__device__ float g_slope[4];

__device__ __forceinline__ float tf32r(float f) {
    uint32_t r;
    asm("cvt.rna.tf32.f32 %0, %1;" : "=r"(r) : "f"(f));
    return __uint_as_float(r);
}

__global__ void prep_kernel(const float* __restrict__ w0, const float* __restrict__ w1,
                            const float* __restrict__ w2, const float* __restrict__ w3,
                            const float* __restrict__ b0, const float* __restrict__ b1,
                            const float* __restrict__ b2, const float* __restrict__ b3,
                            const float* __restrict__ a0, const float* __restrict__ a1,
                            const float* __restrict__ a2, const float* __restrict__ a3)
{
    int t = blockIdx.x * blockDim.x + threadIdx.x;
    if (t < NC * 4 * 256) {
        int h2   = t & 1;
        int pidx = (t >> 1) & 127;       // (kc*4 + tig)*8 + n
        int br   = (t >> 8) & 3;
        int c    = t >> 10;
        int kc   = pidx >> 5;
        int tig  = (pidx >> 3) & 3;
        int n    = pidx & 7;
        int tap  = kc * 8 + tig + h2 * 4;
        float val = 0.f;
        if (tap < 27) {
            const float* w = (br == 0) ? w0 : (br == 1) ? w1 : (br == 2) ? w2 : w3;
            val = tf32r(w[(n * NC + c) * 27 + tap]);
        }
        g_w2[t] = val;
    }
    if (t < 32) {
        const float* b = (t < 8) ? b0 : (t < 16) ? b1 : (t < 24) ? b2 : b3;
        g_bias[t] = b[t & 7];
    }
    if (t < 4) {
        const float* a = (t == 0) ? a0 : (t == 1) ? a1 : (t == 2) ? a2 : a3;
        g_slope[t] = a[0];
    }
}

// ---------- helpers ----------
__device__ __forceinline__ uint32_t smem_u32(const void* p) {
    uint32_t a;
    asm("{ .reg .u64 t; cvta.to.shared.u64 t, %1; cvt.u32.u64 %0, t; }" : "=r"(a) : "l"(p));
    return a;
}
__device__ __forceinline__ void cp16(uint32_t dst, const void* src) {
    asm volatile("cp.async.cg.shared.global [%0], [%1], 16;" :: "r"(dst), "l"(src) : "memory");
}
__device__ __forceinline__ void cp_commit() {
    asm volatile("cp.async.commit_group;" ::: "memory");
}
__device__ __forceinline__ void cp_wait1() {
    asm volatile("cp.async.wait_group 1;" ::: "memory");
}
__device__ __forceinline__ void cp_wait0() {
    asm volatile("cp.async.wait_group 0;" ::: "memory");
}
__device__ __forceinline__ void bar_sync(int id, int cnt) {
    asm volatile("bar.sync %0, %1;" :: "r"(id), "r"(cnt) : "memory");
}
__device__ __forceinline__ uint32_t cvt_tf32(float f) {
    uint32_t r;
    asm("cvt.rna.tf32.f32 %0, %1;" : "=r"(r) : "f"(f));
    return r;
}
__device__ __forceinline__ void mma_tf32(float (&d)[4], uint32_t a0, uint32_t a1,
                                         uint32_t a2, uint32_t a3,
                                         uint32_t b0, uint32_t b1) {
    asm volatile("mma.sync.aligned.m16n8k8.row.col.f32.tf32.tf32.f32 "
                 "{%0,%1,%2,%3}, {%4,%5,%6,%7}, {%8,%9}, {%0,%1,%2,%3};"
                 : "+f"(d[0]), "+f"(d[1]), "+f"(d[2]), "+f"(d[3])
                 : "r"(a0), "r"(a1), "r"(a2), "r"(a3), "r"(b0), "r"(b1));
}

// packed-offset staging: NE entries, u16 chunk indices (0xFFFF = skip)
template<int NE>
__device__ __forceinline__ void stage_x(const uint32_t* pk, uint32_t dst,
                                        const char* xc)
{
    #pragma unroll
    for (int i = 0; i < NE; i++) {
        uint32_t h16 = (pk[i >> 1] >> (16 * (i & 1))) & 0xFFFFu;
        if (h16 != 0xFFFFu) cp16(dst + i * 512, xc + (size_t)h16 * 16);
    }
}

// ===================== main kernel =====================
__global__ __launch_bounds__(128, 5)
void fe_kernel(const float* __restrict__ x, float* __restrict__ out)
{
    __shared__ __align__(16) float sm[SMEM_FLOATS];
    const uint32_t sbase = smem_u32(sm);

    const int tid = threadIdx.x;
    const int br  = tid >> 5;        // warp = branch 0..3
    const int wl  = tid & 31;
    const int tig = wl & 3;          // threadID in group
    const int gid = wl >> 2;         // group id 0..7

    const int tile = blockIdx.x;             // 0..31
    const int tw   = (tile & 1) * TILE_W;
    const int th   = (tile >> 1) * TILE_H;   // 0..60
    const int uv   = blockIdx.y;             // 0..24
    const int u    = uv / 5, v = uv % 5;
    const int b    = blockIdx.z;             // 0..7

    // one-time zero (halo + channel-invariant OOB chunks)
    float4* z = (float4*)sm;
    #pragma unroll
    for (int i = tid; i < SMEM_FLOATS / 4; i += 128)
        z[i] = make_float4(0.f, 0.f, 0.f, 0.f);
    __syncthreads();

    // ---- packed channel-invariant per-lane chunk indices (same as R15) ----
    uint32_t pk[5];
    #pragma unroll
    for (int i = 0; i < 5; i++) pk[i] = 0xFFFFFFFFu;

    const int kbase = (br == 1) ? 288 : 0;
    if (br < 2) {
        #pragma unroll
        for (int i = 0; i < 9; i++) {
            int k = kbase + wl + 32 * i;
            uint32_t val = 0xFFFFu;
            if (k < 540) {
                int row = k / 10, ch = k - row * 10;
                int ab = row / 6, r = row - ab * 6;
                int gu = u + ab / 3 - 1, gv = v + ab % 3 - 1;
                int gh = th + r - 1,     gw = tw - 4 + ch * 4;
                if ((unsigned)gu < 5u && (unsigned)gv < 5u &&
                    (unsigned)gh < 64u && (unsigned)gw < 64u)
                    val = (uint32_t)((((gu * 5 + gv) * 64 + gh) * 64 + gw) >> 2);
            }
            int sh = 16 * (i & 1);
            pk[i >> 1] = (pk[i >> 1] & ~(0xFFFFu << sh)) | (val << sh);
        }
    } else {
        #pragma unroll
        for (int i = 0; i < 6; i++) {
            int k = wl + 32 * i;
            uint32_t val = 0xFFFFu;
            if (k < 180) {
                int row = k / 10, ch = k - row * 10;
                int pkn = row / 6, r = row - pkn * 6;
                int gu = (br == 2) ? (u + pkn - 1) : u;
                int gv = (br == 2) ? v : (v + pkn - 1);
                int gh = th + r - 1, gw = tw - 4 + ch * 4;
                if ((unsigned)gu < 5u && (unsigned)gv < 5u &&
                    (unsigned)gh < 64u && (unsigned)gw < 64u)
                    val = (uint32_t)((((gu * 5 + gv) * 64 + gh) * 64 + gw) >> 2);
            }
            int sh = 16 * (i & 1);
            pk[i >> 1] = (pk[i >> 1] & ~(0xFFFFu << sh)) | (val << sh);
        }
    }

    // ---- channel-invariant per-lane A byte-offsets: off[kc][j], tap = kc*8+tig+4j ----
    int off[4][2];
    #pragma unroll
    for (int kc = 0; kc < 4; kc++) {
        #pragma unroll
        for (int j = 0; j < 2; j++) {
            int tap = kc * 8 + tig + 4 * j;
            int o = 0;
            if (tap < 27) {
                if (br == 0) {
                    int ab = tap / 3, kg = tap % 3;
                    o = ab * 960 + kg * 160;
                } else if (br == 1) {
                    int ab = tap / 3, kg = tap % 3;
                    o = ab * 960 + 160 + (kg - 1) * 4;
                } else {
                    int ka = tap / 9, kb = (tap / 3) % 3, kg = tap % 3;
                    o = ka * 960 + kb * 160 + (kg - 1) * 4;
                }
            }
            off[kc][j] = o;
        }
    }

    const int xoff_f = (br < 2) ? 0 : (br == 2 ? UXY_F : VXY_F);
    uint32_t dstx[2], dstw[2];
    dstx[0] = sbase + xoff_f * 4 + (kbase + wl) * 16;
    dstx[1] = dstx[0] + STAGEB;
    dstw[0] = sbase + (WB_F + br * 256) * 4 + wl * 16;
    dstw[1] = dstw[0] + STAGEB;
    const char* sx_p[2] = { (const char*)(sm + xoff_f),
                            (const char*)(sm + STAGEF + xoff_f) };
    const float* sw_p[2] = { sm + WB_F + br * 256, sm + STAGEF + WB_F + br * 256 };

    const char* xb = (const char*)x + (size_t)b * NC * CHB;
    const char* wb = (const char*)(g_w2 + br * 256);

    // B-pair LDS.64 index (floats): (kc*32 + tig*8 + gid)*2
    const int bidx = (tig * 8 + gid) * 2;
    // A column bases (bytes): col = 4 + wh*16 + gid
    const int cbw0 = (4 + gid) * 4;
    const int cbw1 = (4 + 16 + gid) * 4;

    float d[8][4];
    #pragma unroll
    for (int m = 0; m < 8; m++)
        #pragma unroll
        for (int j = 0; j < 4; j++) d[m][j] = 0.f;

    // ---- stage channel 0 ----
    if (br < 2) stage_x<9>(pk, dstx[0], xb);
    else        stage_x<6>(pk, dstx[0], xb);
    cp16(dstw[0], wb + wl * 16);
    if (wl < 32) cp16(dstw[0] + 512, wb + 512 + wl * 16);  // 64 chunks total
    cp_commit();

    #pragma unroll 1
    for (int c = 0; c < NC; c++) {
        const int s = c & 1;
        if (c < NC - 1) {
            if (br < 2) bar_sync(1, 64); else __syncwarp();
            const char* xc = xb + (size_t)(c + 1) * CHB;
            const char* wc = wb + (size_t)(c + 1) * 4096;
            if (br < 2) stage_x<9>(pk, dstx[s ^ 1], xc);
            else        stage_x<6>(pk, dstx[s ^ 1], xc);
            cp16(dstw[s ^ 1], wc + wl * 16);
            cp16(dstw[s ^ 1] + 512, wc + 512 + wl * 16);
            cp_commit();
            cp_wait1();
        } else {
            cp_wait0();
        }
        if (br < 2) bar_sync(1, 64); else __syncwarp();

        // ---- mma compute: 4 k-chunks x 8 m-tiles ----
        const char*  sx = sx_p[s];
        const float* sw = sw_p[s];
        #pragma unroll
        for (int kc = 0; kc < 4; kc++) {
            float2 bp = *(const float2*)(sw + kc * 64 + bidx);
            uint32_t b0 = __float_as_uint(bp.x);
            uint32_t b1 = __float_as_uint(bp.y);
            const char* p0 = sx + off[kc][0];
            const char* p1 = sx + off[kc][1];
            #pragma unroll
            for (int h = 0; h < 4; h++) {
                const char* q0 = p0 + h * 160;
                const char* q1 = p1 + h * 160;
                {   // wh = 0 -> mtile h*2
                    uint32_t a0 = cvt_tf32(*(const float*)(q0 + cbw0));
                    uint32_t a1 = cvt_tf32(*(const float*)(q0 + cbw0 + 32));
                    uint32_t a2 = cvt_tf32(*(const float*)(q1 + cbw0));
                    uint32_t a3 = cvt_tf32(*(const float*)(q1 + cbw0 + 32));
                    mma_tf32(d[h * 2], a0, a1, a2, a3, b0, b1);
                }
                {   // wh = 1 -> mtile h*2+1
                    uint32_t a0 = cvt_tf32(*(const float*)(q0 + cbw1));
                    uint32_t a1 = cvt_tf32(*(const float*)(q0 + cbw1 + 32));
                    uint32_t a2 = cvt_tf32(*(const float*)(q1 + cbw1));
                    uint32_t a3 = cvt_tf32(*(const float*)(q1 + cbw1 + 32));
                    mma_tf32(d[h * 2 + 1], a0, a1, a2, a3, b0, b1);
                }
            }
        }
    }

    // ---- epilogue: bias + PReLU + store ----
    // d[mt][j]: mt = h*2+wh; j0/j1 -> w = wh*16+gid, oc = tig*2 (+1);
    //           j2/j3 -> w += 8
    const float slope = g_slope[br];
    const int ocb = br * 8 + tig * 2;
    const float b0v = g_bias[ocb];
    const float b1v = g_bias[ocb + 1];
    const size_t base0 = (size_t)b * 32 * CHSTRIDE + (size_t)ocb * CHSTRIDE +
                         (size_t)uv * (NH * NW) + (size_t)th * NW + (size_t)tw;
    #pragma unroll
    for (int mt = 0; mt < 8; mt++) {
        const int h  = mt >> 1;
        const int w0 = (mt & 1) * 16 + gid;
        const size_t rbase = base0 + (size_t)h * NW;
        #pragma unroll
        for (int j = 0; j < 4; j++) {
            const int ww = w0 + ((j >> 1) ? 8 : 0);
            const float bb = (j & 1) ? b1v : b0v;
            const size_t cofs = (j & 1) ? CHSTRIDE : 0;
            float y = d[mt][j] + bb;
            y = (y >= 0.f) ? y : slope * y;
            out[rbase + cofs + ww] = y;
        }
    }
}

extern "C" void kernel_launch(void* const* d_in, const int* in_sizes, int n_in,
                              void* d_out, int out_size)
{
    const float* x = (const float*)d_in[0];

    prep_kernel<<<(NC * 4 * 256 + 255) / 256, 256>>>(
        (const float*)d_in[1], (const float*)d_in[4],
        (const float*)d_in[7], (const float*)d_in[10],
        (const float*)d_in[2], (const float*)d_in[5],
        (const float*)d_in[8], (const float*)d_in[11],
        (const float*)d_in[3], (const float*)d_in[6],
        (const float*)d_in[9], (const float*)d_in[12]);

    dim3 grid(32, 25, 8);   // (hw tiles: 2w x 16h, uv, batch)
    fe_kernel<<<grid, 128>>>(x, (float*)d_out);
}